// round 1
// baseline (speedup 1.0000x reference)
#include <cuda_runtime.h>
#include <math.h>
#include <stdint.h>

// ---------------- problem constants ----------------
#define HID  2048
#define R4   8192          // 4 * HID
#define TLEN 4096
#define IDIM 1024

// ---------------- recurrence kernel config ----------------
#define NBLK   128
#define NTHR   512
#define HPB    16          // h indices per block (2048 / 128)
#define ROWS   64          // gate rows per block (4 * HPB)
#define NCACHE 24          // rows of W_hh cached in SMEM per block (multiple of 4)

#define REC_SMEM_FLOATS (NCACHE * HID + HID + 64 + 16)
#define REC_SMEM_BYTES  (REC_SMEM_FLOATS * 4)

// ---------------- scratch (device globals; no allocation) ----------------
__device__ float    g_xg[(size_t)TLEN * R4];   // precomputed input gates, 128 MB
__device__ float    g_h[2][HID];               // double-buffered hidden state
__device__ unsigned g_barcnt;
__device__ unsigned g_gen;

// ---------------- init ----------------
__global__ void init_kernel() {
    if (threadIdx.x == 0) { g_barcnt = 0u; g_gen = 0u; }
    for (int i = threadIdx.x; i < HID; i += blockDim.x) g_h[0][i] = 0.0f;
}

// ---------------- xg GEMM: g_xg[t][r] = dot(x[t], W_ih[r]) + b_ih[r] + b_hh[r] ----------------
#define BM 64
#define BN 64
#define BK 32
#define GPAD 68   // row pitch in floats; 68*4 bytes is 16B-multiple -> float4-aligned rows

__global__ __launch_bounds__(256) void xg_gemm(const float* __restrict__ x,
                                               const float* __restrict__ W_ih,
                                               const float* __restrict__ b_ih,
                                               const float* __restrict__ b_hh) {
    __shared__ float As[BK * GPAD];   // As[k][t_local]
    __shared__ float Bs[BK * GPAD];   // Bs[k][r_local]
    const int tid = threadIdx.x;
    const int tx = tid & 15;
    const int ty = tid >> 4;
    const int rt = blockIdx.x * BN;   // row-tile base (0..8191)
    const int tt = blockIdx.y * BM;   // time-tile base (0..4095)

    float acc[4][4] = {};

    const int li = tid * 8;           // 2048 elements per tile, 8 per thread
    const int tl = li >> 5;           // local row (t or r), 0..63
    const int kl = li & 31;           // local k, {0,8,16,24}

    for (int k0 = 0; k0 < IDIM; k0 += BK) {
        // load A tile (x) and B tile (W_ih), fully coalesced (float4 x2 per thread)
        const float4* ap = reinterpret_cast<const float4*>(&x[(size_t)(tt + tl) * IDIM + k0 + kl]);
        float4 a0 = __ldg(ap);
        float4 a1 = __ldg(ap + 1);
        const float4* bp = reinterpret_cast<const float4*>(&W_ih[(size_t)(rt + tl) * IDIM + k0 + kl]);
        float4 bb0 = __ldg(bp);
        float4 bb1 = __ldg(bp + 1);

        As[(kl + 0) * GPAD + tl] = a0.x;  As[(kl + 1) * GPAD + tl] = a0.y;
        As[(kl + 2) * GPAD + tl] = a0.z;  As[(kl + 3) * GPAD + tl] = a0.w;
        As[(kl + 4) * GPAD + tl] = a1.x;  As[(kl + 5) * GPAD + tl] = a1.y;
        As[(kl + 6) * GPAD + tl] = a1.z;  As[(kl + 7) * GPAD + tl] = a1.w;

        Bs[(kl + 0) * GPAD + tl] = bb0.x; Bs[(kl + 1) * GPAD + tl] = bb0.y;
        Bs[(kl + 2) * GPAD + tl] = bb0.z; Bs[(kl + 3) * GPAD + tl] = bb0.w;
        Bs[(kl + 4) * GPAD + tl] = bb1.x; Bs[(kl + 5) * GPAD + tl] = bb1.y;
        Bs[(kl + 6) * GPAD + tl] = bb1.z; Bs[(kl + 7) * GPAD + tl] = bb1.w;

        __syncthreads();

        #pragma unroll
        for (int k = 0; k < BK; k++) {
            float4 av = *reinterpret_cast<const float4*>(&As[k * GPAD + ty * 4]);
            float4 bv = *reinterpret_cast<const float4*>(&Bs[k * GPAD + tx * 4]);
            float a[4] = {av.x, av.y, av.z, av.w};
            float b[4] = {bv.x, bv.y, bv.z, bv.w};
            #pragma unroll
            for (int i2 = 0; i2 < 4; i2++)
                #pragma unroll
                for (int j = 0; j < 4; j++)
                    acc[i2][j] += a[i2] * b[j];
        }
        __syncthreads();
    }

    // epilogue: add biases, vectorized store
    const int rbase = rt + tx * 4;
    float bias[4];
    #pragma unroll
    for (int j = 0; j < 4; j++) bias[j] = b_ih[rbase + j] + b_hh[rbase + j];

    #pragma unroll
    for (int i2 = 0; i2 < 4; i2++) {
        const int t = tt + ty * 4 + i2;
        float4 o;
        o.x = acc[i2][0] + bias[0];
        o.y = acc[i2][1] + bias[1];
        o.z = acc[i2][2] + bias[2];
        o.w = acc[i2][3] + bias[3];
        *reinterpret_cast<float4*>(&g_xg[(size_t)t * R4 + rbase]) = o;
    }
}

// ---------------- grid-wide barrier (all blocks co-resident: NBLK=128 <= SM count, 1 block/SM) ----------------
__device__ __forceinline__ void grid_sync_() {
    __syncthreads();
    if (threadIdx.x == 0) {
        __threadfence();
        unsigned g = atomicAdd(&g_gen, 0u);
        if (atomicAdd(&g_barcnt, 1u) == NBLK - 1u) {
            atomicExch(&g_barcnt, 0u);
            __threadfence();
            atomicExch(&g_gen, g + 1u);
        } else {
            while (atomicAdd(&g_gen, 0u) == g) { }
        }
    }
    __syncthreads();
}

__device__ __forceinline__ float sigmoidf_(float v) { return 1.0f / (1.0f + expf(-v)); }

// ---------------- persistent LSTM recurrence ----------------
__global__ __launch_bounds__(NTHR, 1) void lstm_rec(const float* __restrict__ W_hh) {
    extern __shared__ float smem[];
    float* wc   = smem;                    // NCACHE * HID
    float* h_sh = smem + NCACHE * HID;     // HID
    float* g_sh = h_sh + HID;              // 64 gate pre-activations
    float* c_sh = g_sh + 64;               // 16 cell states (block-private, persistent)

    const int tid   = threadIdx.x;
    const int hbase = blockIdx.x * HPB;

    // stage NCACHE rows of this block's W_hh slice into SMEM (once)
    for (int idx = tid; idx < NCACHE * HID; idx += NTHR) {
        const int lr   = idx >> 11;        // local row 0..NCACHE-1
        const int col  = idx & (HID - 1);
        const int gate = lr >> 4;
        const int hl   = lr & 15;
        const int row  = gate * HID + hbase + hl;
        wc[idx] = W_hh[(size_t)row * HID + col];
    }
    if (tid < HPB) c_sh[tid] = 0.0f;

    const int warp = tid >> 5;
    const int lane = tid & 31;
    const int lr0  = warp * 4;             // this warp's 4 rows (never crosses a gate boundary)
    const int gate0 = lr0 >> 4;
    const int hl0   = lr0 & 15;
    const size_t rowg0 = (size_t)(gate0 * HID + hbase + hl0);
    const float* wp0 = W_hh + rowg0 * HID; // global pointers for uncached rows
    const bool use_sm = (lr0 + 3 < NCACHE);
    const float* ws0 = wc + lr0 * HID;

    for (int t = 0; t < TLEN; t++) {
        grid_sync_();                       // h(t) from all blocks now visible

        const float* hsrc = g_h[t & 1];
        for (int i = tid; i < HID; i += NTHR) h_sh[i] = hsrc[i];
        __syncthreads();

        float a0 = 0.f, a1 = 0.f, a2 = 0.f, a3 = 0.f;
        if (use_sm) {
            #pragma unroll 8
            for (int j = lane; j < HID; j += 32) {
                const float hv = h_sh[j];
                a0 += ws0[j] * hv;
                a1 += ws0[HID + j] * hv;
                a2 += ws0[2 * HID + j] * hv;
                a3 += ws0[3 * HID + j] * hv;
            }
        } else {
            #pragma unroll 4
            for (int j = lane; j < HID; j += 32) {
                const float hv = h_sh[j];
                a0 += __ldg(wp0 + j) * hv;
                a1 += __ldg(wp0 + HID + j) * hv;
                a2 += __ldg(wp0 + 2 * HID + j) * hv;
                a3 += __ldg(wp0 + 3 * HID + j) * hv;
            }
        }

        #pragma unroll
        for (int off = 16; off; off >>= 1) {
            a0 += __shfl_xor_sync(0xFFFFFFFFu, a0, off);
            a1 += __shfl_xor_sync(0xFFFFFFFFu, a1, off);
            a2 += __shfl_xor_sync(0xFFFFFFFFu, a2, off);
            a3 += __shfl_xor_sync(0xFFFFFFFFu, a3, off);
        }
        if (lane == 0) {
            const float* xgrow = g_xg + (size_t)t * R4;
            g_sh[lr0 + 0] = a0 + xgrow[rowg0 + 0];
            g_sh[lr0 + 1] = a1 + xgrow[rowg0 + 1];
            g_sh[lr0 + 2] = a2 + xgrow[rowg0 + 2];
            g_sh[lr0 + 3] = a3 + xgrow[rowg0 + 3];
        }
        __syncthreads();

        if (tid < HPB) {
            const float iv = sigmoidf_(g_sh[tid]);
            const float fv = sigmoidf_(g_sh[16 + tid]);
            const float gv = tanhf(g_sh[32 + tid]);
            const float ov = sigmoidf_(g_sh[48 + tid]);
            const float c  = fv * c_sh[tid] + iv * gv;
            c_sh[tid] = c;
            g_h[(t + 1) & 1][hbase + tid] = ov * tanhf(c);
        }
        // next grid_sync_ publishes h(t+1)
    }
}

// ---------------- output layer: out = dot(h_T, W_out) + b_out ----------------
__global__ void out_kernel(const float* __restrict__ W_out,
                           const float* __restrict__ b_out,
                           float* __restrict__ out) {
    __shared__ float red[8];
    const int tid = threadIdx.x;   // 256 threads
    const float* hfin = g_h[0];    // TLEN even -> final h in buffer 0
    float s = 0.f;
    for (int j = tid; j < HID; j += 256) s += hfin[j] * W_out[j];
    #pragma unroll
    for (int off = 16; off; off >>= 1) s += __shfl_xor_sync(0xFFFFFFFFu, s, off);
    if ((tid & 31) == 0) red[tid >> 5] = s;
    __syncthreads();
    if (tid < 8) {
        float v = red[tid];
        #pragma unroll
        for (int off = 4; off; off >>= 1) v += __shfl_xor_sync(0xFFu, v, off);
        if (tid == 0) out[0] = v + b_out[0];
    }
}

// ---------------- launch ----------------
extern "C" void kernel_launch(void* const* d_in, const int* in_sizes, int n_in,
                              void* d_out, int out_size) {
    const float* x     = (const float*)d_in[0];
    const float* W_ih  = (const float*)d_in[1];
    const float* W_hh  = (const float*)d_in[2];
    const float* b_ih  = (const float*)d_in[3];
    const float* b_hh  = (const float*)d_in[4];
    const float* W_out = (const float*)d_in[5];
    const float* b_out = (const float*)d_in[6];
    float* out = (float*)d_out;

    init_kernel<<<1, 256>>>();

    dim3 ggrid(R4 / BN, TLEN / BM);
    xg_gemm<<<ggrid, 256>>>(x, W_ih, b_ih, b_hh);

    cudaFuncSetAttribute(lstm_rec, cudaFuncAttributeMaxDynamicSharedMemorySize, REC_SMEM_BYTES);
    lstm_rec<<<NBLK, NTHR, REC_SMEM_BYTES>>>(W_hh);

    out_kernel<<<1, 256>>>(W_out, b_out, out);
}

// round 3
// speedup vs baseline: 1.3732x; 1.3732x over previous
#include <cuda_runtime.h>
#include <cuda_fp16.h>
#include <math.h>
#include <stdint.h>

typedef unsigned long long ull;

// ---------------- problem constants ----------------
#define HID  2048
#define R4   8192          // 4 * HID
#define TLEN 4096
#define IDIM 1024

// ---------------- recurrence kernel config ----------------
#define NBLK   128
#define NTHR   512
#define HPB    16          // h indices per block (2048 / 128)
#define NCACHE 48          // rows of W_hh (fp16) cached in SMEM per block

// smem: 48 rows * 2048 halfs (196608 B) + h 2048 f + g 64 f + c 16 f
#define REC_SMEM_BYTES (NCACHE * HID * 2 + (HID + 64 + 16) * 4)

// ---------------- scratch (device globals; no allocation) ----------------
__device__ float    g_xg[(size_t)TLEN * R4];      // precomputed input gates, 128 MB
__device__ __half   g_whh[(size_t)R4 * HID];      // fp16 copy of W_hh, 32 MB
__device__ float    g_h[2][HID];                  // double-buffered hidden state
__device__ unsigned g_barcnt;
__device__ unsigned g_gen;

// ---------------- init ----------------
__global__ void init_kernel() {
    if (threadIdx.x == 0) { g_barcnt = 0u; g_gen = 0u; }
    for (int i = threadIdx.x; i < HID; i += blockDim.x) g_h[0][i] = 0.0f;
}

// ---------------- W_hh fp32 -> fp16 ----------------
__global__ void prep_whh(const float* __restrict__ W_hh) {
    const size_t n2 = (size_t)R4 * HID / 2;   // half2 count
    const size_t stride = (size_t)gridDim.x * blockDim.x;
    for (size_t i = (size_t)blockIdx.x * blockDim.x + threadIdx.x; i < n2; i += stride) {
        float2 v = reinterpret_cast<const float2*>(W_hh)[i];
        reinterpret_cast<__half2*>(g_whh)[i] = __floats2half2_rn(v.x, v.y);
    }
}

// ---------------- packed f32x2 helpers ----------------
__device__ __forceinline__ void fma2_(ull& acc, ull a, ull b) {
    asm("fma.rn.f32x2 %0, %1, %2, %0;" : "+l"(acc) : "l"(a), "l"(b));
}
__device__ __forceinline__ ull h2_to_f2(unsigned h2) {
    ull r;
    asm("{\n\t"
        ".reg .b16 lo, hi;\n\t"
        ".reg .f32 flo, fhi;\n\t"
        "mov.b32 {lo, hi}, %1;\n\t"
        "cvt.f32.f16 flo, lo;\n\t"
        "cvt.f32.f16 fhi, hi;\n\t"
        "mov.b64 %0, {flo, fhi};\n\t"
        "}" : "=l"(r) : "r"(h2));
    return r;
}

// ---------------- xg GEMM: 128x128x16 tiles, 8x8 micro ----------------
#define GBM 128
#define GBN 128
#define GBK 16
#define GAP 132   // smem pitch in floats (multiple of 4 -> float4 aligned)

__global__ __launch_bounds__(256) void xg_gemm(const float* __restrict__ x,
                                               const float* __restrict__ W_ih,
                                               const float* __restrict__ b_ih,
                                               const float* __restrict__ b_hh) {
    __shared__ float As[GBK * GAP];   // As[k][m]
    __shared__ float Bs[GBK * GAP];   // Bs[k][n]
    const int tid = threadIdx.x;
    const int tx = tid & 15;
    const int ty = tid >> 4;
    const int rt = blockIdx.x * GBN;
    const int tt = blockIdx.y * GBM;

    const int lr = tid >> 2;          // load row 0..63
    const int lc = (tid & 3) * 4;     // load k-group {0,4,8,12}

    float acc[2][2][4][4];
    #pragma unroll
    for (int a = 0; a < 2; a++)
        #pragma unroll
        for (int b = 0; b < 2; b++)
            #pragma unroll
            for (int i = 0; i < 4; i++)
                #pragma unroll
                for (int j = 0; j < 4; j++) acc[a][b][i][j] = 0.f;

    for (int k0 = 0; k0 < IDIM; k0 += GBK) {
        float4 a0 = __ldg(reinterpret_cast<const float4*>(&x[(size_t)(tt + lr) * IDIM + k0 + lc]));
        float4 a1 = __ldg(reinterpret_cast<const float4*>(&x[(size_t)(tt + lr + 64) * IDIM + k0 + lc]));
        float4 w0 = __ldg(reinterpret_cast<const float4*>(&W_ih[(size_t)(rt + lr) * IDIM + k0 + lc]));
        float4 w1 = __ldg(reinterpret_cast<const float4*>(&W_ih[(size_t)(rt + lr + 64) * IDIM + k0 + lc]));

        As[(lc + 0) * GAP + lr] = a0.x; As[(lc + 1) * GAP + lr] = a0.y;
        As[(lc + 2) * GAP + lr] = a0.z; As[(lc + 3) * GAP + lr] = a0.w;
        As[(lc + 0) * GAP + lr + 64] = a1.x; As[(lc + 1) * GAP + lr + 64] = a1.y;
        As[(lc + 2) * GAP + lr + 64] = a1.z; As[(lc + 3) * GAP + lr + 64] = a1.w;

        Bs[(lc + 0) * GAP + lr] = w0.x; Bs[(lc + 1) * GAP + lr] = w0.y;
        Bs[(lc + 2) * GAP + lr] = w0.z; Bs[(lc + 3) * GAP + lr] = w0.w;
        Bs[(lc + 0) * GAP + lr + 64] = w1.x; Bs[(lc + 1) * GAP + lr + 64] = w1.y;
        Bs[(lc + 2) * GAP + lr + 64] = w1.z; Bs[(lc + 3) * GAP + lr + 64] = w1.w;

        __syncthreads();

        #pragma unroll
        for (int k = 0; k < GBK; k++) {
            float4 av0 = *reinterpret_cast<const float4*>(&As[k * GAP + ty * 4]);
            float4 av1 = *reinterpret_cast<const float4*>(&As[k * GAP + 64 + ty * 4]);
            float4 bv0 = *reinterpret_cast<const float4*>(&Bs[k * GAP + tx * 4]);
            float4 bv1 = *reinterpret_cast<const float4*>(&Bs[k * GAP + 64 + tx * 4]);
            float am[2][4] = {{av0.x, av0.y, av0.z, av0.w}, {av1.x, av1.y, av1.z, av1.w}};
            float bn[2][4] = {{bv0.x, bv0.y, bv0.z, bv0.w}, {bv1.x, bv1.y, bv1.z, bv1.w}};
            #pragma unroll
            for (int a = 0; a < 2; a++)
                #pragma unroll
                for (int i = 0; i < 4; i++)
                    #pragma unroll
                    for (int b = 0; b < 2; b++)
                        #pragma unroll
                        for (int j = 0; j < 4; j++)
                            acc[a][b][i][j] += am[a][i] * bn[b][j];
        }
        __syncthreads();
    }

    #pragma unroll
    for (int b = 0; b < 2; b++) {
        const int rbase = rt + b * 64 + tx * 4;
        float bias[4];
        #pragma unroll
        for (int j = 0; j < 4; j++) bias[j] = b_ih[rbase + j] + b_hh[rbase + j];
        #pragma unroll
        for (int a = 0; a < 2; a++) {
            #pragma unroll
            for (int i = 0; i < 4; i++) {
                const int t = tt + a * 64 + ty * 4 + i;
                float4 o;
                o.x = acc[a][b][i][0] + bias[0];
                o.y = acc[a][b][i][1] + bias[1];
                o.z = acc[a][b][i][2] + bias[2];
                o.w = acc[a][b][i][3] + bias[3];
                *reinterpret_cast<float4*>(&g_xg[(size_t)t * R4 + rbase]) = o;
            }
        }
    }
}

// ---------------- grid-wide barrier (R1-proven; all blocks co-resident) ----------------
__device__ __forceinline__ void grid_sync_() {
    __syncthreads();
    if (threadIdx.x == 0) {
        __threadfence();
        unsigned g = atomicAdd(&g_gen, 0u);
        if (atomicAdd(&g_barcnt, 1u) == NBLK - 1u) {
            atomicExch(&g_barcnt, 0u);
            __threadfence();
            atomicExch(&g_gen, g + 1u);
        } else {
            while (atomicAdd(&g_gen, 0u) == g) { }
        }
    }
    __syncthreads();
}

__device__ __forceinline__ float sigmoidf_(float v) { return 1.0f / (1.0f + expf(-v)); }

// ---------------- 4-row dot (fp16 weights, f32x2 accumulation) ----------------
template<bool SM>
__device__ __forceinline__ void dot4rows(const __half* __restrict__ base,
                                         const float* __restrict__ h_sh,
                                         int lane, float out[4]) {
    ull acc[4][2] = {{0ull,0ull},{0ull,0ull},{0ull,0ull},{0ull,0ull}};
    #pragma unroll
    for (int pass = 0; pass < 2; pass++) {
        ull hh[4][4];
        #pragma unroll
        for (int c = 0; c < 4; c++) {
            const ulonglong2* hp =
                reinterpret_cast<const ulonglong2*>(h_sh + pass * 1024 + c * 256 + lane * 8);
            ulonglong2 v0 = hp[0];
            ulonglong2 v1 = hp[1];
            hh[c][0] = v0.x; hh[c][1] = v0.y; hh[c][2] = v1.x; hh[c][3] = v1.y;
        }
        #pragma unroll
        for (int r = 0; r < 4; r++) {
            #pragma unroll
            for (int c = 0; c < 4; c++) {
                const uint4* wp = reinterpret_cast<const uint4*>(
                    base + r * HID + pass * 1024 + c * 256 + lane * 8);
                uint4 w = SM ? *wp : __ldg(wp);
                fma2_(acc[r][0], h2_to_f2(w.x), hh[c][0]);
                fma2_(acc[r][1], h2_to_f2(w.y), hh[c][1]);
                fma2_(acc[r][0], h2_to_f2(w.z), hh[c][2]);
                fma2_(acc[r][1], h2_to_f2(w.w), hh[c][3]);
            }
        }
    }
    #pragma unroll
    for (int r = 0; r < 4; r++) {
        ull s;
        asm("add.rn.f32x2 %0, %1, %2;" : "=l"(s) : "l"(acc[r][0]), "l"(acc[r][1]));
        float lo, hi;
        asm("mov.b64 {%0, %1}, %2;" : "=f"(lo), "=f"(hi) : "l"(s));
        out[r] = lo + hi;
    }
}

// ---------------- persistent LSTM recurrence ----------------
__global__ __launch_bounds__(NTHR, 1) void lstm_rec() {
    extern __shared__ float smem[];
    __half* wc   = reinterpret_cast<__half*>(smem);          // NCACHE * HID halfs
    float*  h_sh = smem + NCACHE * HID / 2;                  // HID floats
    float*  g_sh = h_sh + HID;                               // 64 gate pre-activations
    float*  c_sh = g_sh + 64;                                // 16 cell states

    const int tid   = threadIdx.x;
    const int hbase = blockIdx.x * HPB;

    // stage NCACHE rows (gates i,f,g for this block's slice) into SMEM as fp16
    for (int idx = tid; idx < NCACHE * HID / 8; idx += NTHR) {
        const int lr  = idx >> 8;               // local row (256 uint4 per row)
        const int col = (idx & 255) * 8;        // half index within row
        const int gate = lr >> 4;
        const int hl   = lr & 15;
        const size_t row = (size_t)(gate * HID + hbase + hl);
        reinterpret_cast<uint4*>(wc + (size_t)lr * HID)[col / 8] =
            __ldg(reinterpret_cast<const uint4*>(g_whh + row * HID + col));
    }
    if (tid < HPB) c_sh[tid] = 0.0f;

    const int warp = tid >> 5;
    const int lane = tid & 31;
    const int lr0  = warp * 4;                  // 4 rows per warp, same gate
    const int gate0 = lr0 >> 4;
    const int hl0   = lr0 & 15;
    const size_t rowg0 = (size_t)(gate0 * HID + hbase + hl0);
    const __half* sm_base = wc + (size_t)lr0 * HID;
    const __half* gl_base = g_whh + rowg0 * HID;
    const bool use_sm = (lr0 + 3 < NCACHE);

    for (int t = 0; t < TLEN; t++) {
        // prefetch xg row (h-independent; hides DRAM latency behind barrier)
        float4 xgv = make_float4(0.f, 0.f, 0.f, 0.f);
        if (lane == 0)
            xgv = __ldg(reinterpret_cast<const float4*>(g_xg + (size_t)t * R4 + rowg0));

        grid_sync_();                            // h(t) from all blocks now visible

        const float* hsrc = g_h[t & 1];
        *reinterpret_cast<float4*>(h_sh + tid * 4) =
            *reinterpret_cast<const float4*>(hsrc + tid * 4);
        __syncthreads();

        float a[4];
        if (use_sm) dot4rows<true >(sm_base, h_sh, lane, a);
        else        dot4rows<false>(gl_base, h_sh, lane, a);

        #pragma unroll
        for (int off = 16; off; off >>= 1) {
            a[0] += __shfl_xor_sync(0xFFFFFFFFu, a[0], off);
            a[1] += __shfl_xor_sync(0xFFFFFFFFu, a[1], off);
            a[2] += __shfl_xor_sync(0xFFFFFFFFu, a[2], off);
            a[3] += __shfl_xor_sync(0xFFFFFFFFu, a[3], off);
        }
        if (lane == 0) {
            g_sh[lr0 + 0] = a[0] + xgv.x;
            g_sh[lr0 + 1] = a[1] + xgv.y;
            g_sh[lr0 + 2] = a[2] + xgv.z;
            g_sh[lr0 + 3] = a[3] + xgv.w;
        }
        __syncthreads();

        if (tid < HPB) {
            const float iv = sigmoidf_(g_sh[tid]);
            const float fv = sigmoidf_(g_sh[16 + tid]);
            const float gv = tanhf(g_sh[32 + tid]);
            const float ov = sigmoidf_(g_sh[48 + tid]);
            const float c  = fv * c_sh[tid] + iv * gv;
            c_sh[tid] = c;
            g_h[(t + 1) & 1][hbase + tid] = ov * tanhf(c);
        }
    }
}

// ---------------- output layer ----------------
__global__ void out_kernel(const float* __restrict__ W_out,
                           const float* __restrict__ b_out,
                           float* __restrict__ out) {
    __shared__ float red[8];
    const int tid = threadIdx.x;   // 256 threads
    const float* hfin = g_h[0];    // TLEN even -> final h in buffer 0
    float s = 0.f;
    for (int j = tid; j < HID; j += 256) s += hfin[j] * W_out[j];
    #pragma unroll
    for (int off = 16; off; off >>= 1) s += __shfl_xor_sync(0xFFFFFFFFu, s, off);
    if ((tid & 31) == 0) red[tid >> 5] = s;
    __syncthreads();
    if (tid < 8) {
        float v = red[tid];
        #pragma unroll
        for (int off = 4; off; off >>= 1) v += __shfl_xor_sync(0xFFu, v, off);
        if (tid == 0) out[0] = v + b_out[0];
    }
}

// ---------------- launch ----------------
extern "C" void kernel_launch(void* const* d_in, const int* in_sizes, int n_in,
                              void* d_out, int out_size) {
    const float* x     = (const float*)d_in[0];
    const float* W_ih  = (const float*)d_in[1];
    const float* W_hh  = (const float*)d_in[2];
    const float* b_ih  = (const float*)d_in[3];
    const float* b_hh  = (const float*)d_in[4];
    const float* W_out = (const float*)d_in[5];
    const float* b_out = (const float*)d_in[6];
    float* out = (float*)d_out;

    init_kernel<<<1, 256>>>();
    prep_whh<<<2048, 256>>>(W_hh);

    dim3 ggrid(R4 / GBN, TLEN / GBM);
    xg_gemm<<<ggrid, 256>>>(x, W_ih, b_ih, b_hh);

    cudaFuncSetAttribute(lstm_rec, cudaFuncAttributeMaxDynamicSharedMemorySize, REC_SMEM_BYTES);
    lstm_rec<<<NBLK, NTHR, REC_SMEM_BYTES>>>();

    out_kernel<<<1, 256>>>(W_out, b_out, out);
}